// round 4
// baseline (speedup 1.0000x reference)
#include <cuda_runtime.h>
#include <math.h>

#define H_      384
#define W_      512
#define HW_     (H_ * W_)        /* 196608 */
#define HW4_    (HW_ / 4)        /* 49152 float4 groups per (n,b) plane */
#define B_      4
#define NPRED_  12
#define NBXH    48               /* blocks along hw per (pred, batch) */
#define NBX     (NBXH * B_)      /* 192 partials per pred */
#define NTHR    256

/* per-(pred, block) partials — device globals, no allocation */
__device__ float    g_psum[NPRED_ * NBX];
__device__ float    g_pcnt[NPRED_ * NBX];
__device__ float    g_pmask[NBX];
__device__ unsigned g_ticket;    /* zero-initialized; reset by last block */

__device__ __forceinline__ float lse2f(float x, float y) {
    float m = fmaxf(x, y);
    float d = fabsf(x - y);
    return m + __logf(1.0f + __expf(-d));
}

/* NOTE: log_b[:,1] = clip(info[:,3], 0.0, 0.0) == 0 for all finite inputs,
   so info channel 3 is never read: lb1 = 0, exp(-lb1) = 1, t1 = a1 - ln2. */

__global__ __launch_bounds__(NTHR, 5) void loss_fused_kernel(
    const float* __restrict__ flow,   /* (12,4,2,H,W) */
    const float* __restrict__ info,   /* (12,4,4,H,W) */
    const float* __restrict__ gt,     /* (4,2,H,W) */
    const float* __restrict__ valid,  /* (4,1,H,W) */
    float* __restrict__ out)
{
    const int n = blockIdx.y;
    const int b = blockIdx.z;
    const float LN2   = 0.69314718055994530942f;
    const float MAXF2 = (float)(H_ * W_);   /* mag < sqrt(H*W)  <=>  mag^2 < H*W */

    /* loop-invariant (uniform) base pointers */
    const float* __restrict__ gtx = gt    + (size_t)(b * 2 + 0) * HW_;
    const float* __restrict__ gty = gt    + (size_t)(b * 2 + 1) * HW_;
    const float* __restrict__ vld = valid + (size_t)b * HW_;
    const float* __restrict__ fx  = flow  + (size_t)((n * B_ + b) * 2) * HW_;
    const float* __restrict__ fy  = fx + HW_;
    const float* __restrict__ ia0 = info  + (size_t)((n * B_ + b) * 4) * HW_;
    const float* __restrict__ ia1 = ia0 + HW_;
    const float* __restrict__ ib2 = ia0 + 2 * HW_;
    /* info channel 3 intentionally NOT loaded: clip(.,0,0) == 0 */

    float sum  = 0.0f;
    int   cnt  = 0;
    int   mcnt = 0;

    #pragma unroll 2
    for (int g = blockIdx.x * NTHR + threadIdx.x; g < HW4_; g += NBXH * NTHR) {
        const int hw = g * 4;

        /* gt/valid: reused by all 12 preds — keep L2-cached */
        const float4 gx4 = __ldg((const float4*)(gtx + hw));
        const float4 gy4 = __ldg((const float4*)(gty + hw));
        const float4 vv4 = __ldg((const float4*)(vld + hw));

        /* flow/info: streamed once — evict-first */
        const float4 fx4 = __ldcs((const float4*)(fx  + hw));
        const float4 fy4 = __ldcs((const float4*)(fy  + hw));
        const float4 a04 = __ldcs((const float4*)(ia0 + hw));
        const float4 a14 = __ldcs((const float4*)(ia1 + hw));
        const float4 b24 = __ldcs((const float4*)(ib2 + hw));

        float gxv[4], gyv[4], vvv[4], fxv[4], fyv[4], a0v[4], a1v[4], b2v[4];
        *(float4*)gxv = gx4;  *(float4*)gyv = gy4;  *(float4*)vvv = vv4;
        *(float4*)fxv = fx4;  *(float4*)fyv = fy4;
        *(float4*)a0v = a04;  *(float4*)a1v = a14;
        *(float4*)b2v = b24;

        #pragma unroll
        for (int j = 0; j < 4; j++) {
            const float gx = gxv[j], gy = gyv[j];
            const bool m1 = (gx * gx + gy * gy < MAXF2) && (vvv[j] != 0.0f);
            mcnt += m1 ? 1 : 0;

            const float a0  = a0v[j];
            const float a1  = a1v[j];
            const float lb0 = fminf(fmaxf(b2v[j], 0.0f), 10.0f);
            const float eb0 = __expf(-lb0);

            const float lse_a = lse2f(a0, a1);
            const float t0 = a0 - LN2 - lb0;
            const float t1 = a1 - LN2;          /* lb1 == 0 */

            const float dx  = fabsf(gx - fxv[j]);
            const float nfx = lse_a - lse2f(t0 - dx * eb0, t1 - dx);
            const float dy  = fabsf(gy - fyv[j]);
            const float nfy = lse_a - lse2f(t0 - dy * eb0, t1 - dy);

            if (isfinite(nfx) && m1) { sum += nfx; cnt++; }
            if (isfinite(nfy) && m1) { sum += nfy; cnt++; }
        }
    }

    /* ---- block reduction ---- */
    float fcnt  = (float)cnt;
    float fmcnt = (float)mcnt;
    #pragma unroll
    for (int o = 16; o > 0; o >>= 1) {
        sum   += __shfl_down_sync(0xFFFFFFFFu, sum,   o);
        fcnt  += __shfl_down_sync(0xFFFFFFFFu, fcnt,  o);
        fmcnt += __shfl_down_sync(0xFFFFFFFFu, fmcnt, o);
    }
    __shared__ float ssum[NTHR / 32], scnt[NTHR / 32], smc[NTHR / 32];
    const int wid  = threadIdx.x >> 5;
    const int lane = threadIdx.x & 31;
    if (lane == 0) { ssum[wid] = sum; scnt[wid] = fcnt; smc[wid] = fmcnt; }
    __syncthreads();

    const int pblk = b * NBXH + blockIdx.x;   /* 0..191 partial slot */
    if (threadIdx.x == 0) {
        float bs = 0.0f, bc = 0.0f, bm = 0.0f;
        #pragma unroll
        for (int w = 0; w < NTHR / 32; w++) { bs += ssum[w]; bc += scnt[w]; bm += smc[w]; }
        g_psum[n * NBX + pblk] = bs;
        g_pcnt[n * NBX + pblk] = bc;
        if (n == 0) g_pmask[pblk] = bm;
    }

    /* ---- last-block-done final reduction (deterministic: fixed partials,
            fixed reduction order; only the reducing block's identity varies) ---- */
    __shared__ unsigned s_islast;
    __threadfence();
    if (threadIdx.x == 0) {
        unsigned tkt = atomicAdd(&g_ticket, 1u);
        s_islast = (tkt == (unsigned)(NPRED_ * NBX - 1)) ? 1u : 0u;
    }
    __syncthreads();
    if (!s_islast) return;

    const int t = threadIdx.x;
    __shared__ float s_res[NPRED_];
    __shared__ float s_m[2];

    if (t < 192) {
        /* 16 threads per pred, each sums 12 partials */
        const int pred = t >> 4;
        const int sub  = t & 15;
        float s = 0.0f, c = 0.0f;
        #pragma unroll
        for (int i = sub; i < NBX; i += 16) {
            s += g_psum[pred * NBX + i];
            c += g_pcnt[pred * NBX + i];
        }
        #pragma unroll
        for (int o = 8; o > 0; o >>= 1) {
            s += __shfl_down_sync(0xFFFFFFFFu, s, o, 16);
            c += __shfl_down_sync(0xFFFFFFFFu, c, o, 16);
        }
        if (sub == 0) s_res[pred] = s / fmaxf(c, 1.0f);
    } else {
        /* threads 192..255 reduce the 192 mask partials */
        const int i0 = t - 192;
        float m = 0.0f;
        #pragma unroll
        for (int i = i0; i < NBX; i += 64) m += g_pmask[i];
        #pragma unroll
        for (int o = 16; o > 0; o >>= 1) m += __shfl_down_sync(0xFFFFFFFFu, m, o);
        if (((t - 192) & 31) == 0) s_m[(t - 192) >> 5] = m;
    }
    __syncthreads();
    if (t == 0) {
        float loss = 0.0f;
        #pragma unroll
        for (int i = 0; i < NPRED_; i++) loss += s_res[i];
        const float mean_mask = (s_m[0] + s_m[1]) * (1.0f / (float)(B_ * HW_));
        out[0] = (mean_mask < 0.25f) ? 0.0f : loss;
        g_ticket = 0;   /* reset for the next graph replay */
    }
}

extern "C" void kernel_launch(void* const* d_in, const int* in_sizes, int n_in,
                              void* d_out, int out_size) {
    const float* flow  = (const float*)d_in[0];  /* flow_preds (12,4,2,384,512) */
    const float* info  = (const float*)d_in[1];  /* info_preds (12,4,4,384,512) */
    const float* gt    = (const float*)d_in[2];  /* flow_gt    (4,2,384,512)    */
    const float* valid = (const float*)d_in[3];  /* valid      (4,1,384,512)    */
    (void)in_sizes; (void)n_in; (void)out_size;

    dim3 grid(NBXH, NPRED_, B_);
    loss_fused_kernel<<<grid, NTHR>>>(flow, info, gt, valid, (float*)d_out);
}

// round 5
// speedup vs baseline: 1.0338x; 1.0338x over previous
#include <cuda_runtime.h>
#include <math.h>

#define H_      384
#define W_      512
#define HW_     (H_ * W_)        /* 196608 */
#define HW4_    (HW_ / 4)        /* 49152 float4 groups per (n,b) plane */
#define B_      4
#define NPRED_  12
#define NBXH    48               /* blocks along hw per (pred, batch) */
#define NBX     (NBXH * B_)      /* 192 partials per pred */
#define NTHR    256

/* per-(pred, block) partials — device globals, no allocation */
__device__ float    g_psum[NPRED_ * NBX];
__device__ float    g_pcnt[NPRED_ * NBX];
__device__ float    g_pmask[NBX];
__device__ unsigned g_ticket;    /* zero-initialized; reset by last block */

/* NOTE: log_b[:,1] = clip(info[:,3], 0.0, 0.0) == 0 for all finite inputs,
   so info channel 3 is never read (lb1 = 0, exp(-lb1) = 1).
   Algebra (per pixel, D = a0-a1, lb0 = clip(info2,0,10)):
     nf_c = base + d_c - ln2*( relu(S_c) + log2(1 + 2^-|S_c|) )
     S_c  = dtp + d_c*w,   dtp = (D - lb0)*log2e,   w = (1-2^(-lb0*log2e))*log2e
     base = relu(D) + ln2*( log2(1 + 2^-|D*log2e|) + 1 )
   base/dtp/w are shared between the x and y flow components. */

__global__ __launch_bounds__(NTHR, 4) void loss_fused_kernel(
    const float* __restrict__ flow,   /* (12,4,2,H,W) */
    const float* __restrict__ info,   /* (12,4,4,H,W) */
    const float* __restrict__ gt,     /* (4,2,H,W) */
    const float* __restrict__ valid,  /* (4,1,H,W) */
    float* __restrict__ out)
{
    const int n = blockIdx.y;
    const int b = blockIdx.z;
    const float L2E   = 1.44269504088896340736f;  /* log2(e) */
    const float LN2   = 0.69314718055994530942f;
    const float MAXF2 = (float)(H_ * W_);   /* mag < sqrt(H*W)  <=>  mag^2 < H*W */

    /* loop-invariant (uniform) base pointers */
    const float* __restrict__ gtx = gt    + (size_t)(b * 2 + 0) * HW_;
    const float* __restrict__ gty = gt    + (size_t)(b * 2 + 1) * HW_;
    const float* __restrict__ vld = valid + (size_t)b * HW_;
    const float* __restrict__ fx  = flow  + (size_t)((n * B_ + b) * 2) * HW_;
    const float* __restrict__ fy  = fx + HW_;
    const float* __restrict__ ia0 = info  + (size_t)((n * B_ + b) * 4) * HW_;
    const float* __restrict__ ia1 = ia0 + HW_;
    const float* __restrict__ ib2 = ia0 + 2 * HW_;

    float sum  = 0.0f;
    float cnt  = 0.0f;
    float mcnt = 0.0f;

    #pragma unroll 2
    for (int g = blockIdx.x * NTHR + threadIdx.x; g < HW4_; g += NBXH * NTHR) {
        const int hw = g * 4;

        /* gt/valid: reused by all 12 preds — keep L2-cached */
        const float4 gx4 = __ldg((const float4*)(gtx + hw));
        const float4 gy4 = __ldg((const float4*)(gty + hw));
        const float4 vv4 = __ldg((const float4*)(vld + hw));

        /* flow/info: streamed once — evict-first */
        const float4 fx4 = __ldcs((const float4*)(fx  + hw));
        const float4 fy4 = __ldcs((const float4*)(fy  + hw));
        const float4 a04 = __ldcs((const float4*)(ia0 + hw));
        const float4 a14 = __ldcs((const float4*)(ia1 + hw));
        const float4 b24 = __ldcs((const float4*)(ib2 + hw));

        float gxv[4], gyv[4], vvv[4], fxv[4], fyv[4], a0v[4], a1v[4], b2v[4];
        *(float4*)gxv = gx4;  *(float4*)gyv = gy4;  *(float4*)vvv = vv4;
        *(float4*)fxv = fx4;  *(float4*)fyv = fy4;
        *(float4*)a0v = a04;  *(float4*)a1v = a14;
        *(float4*)b2v = b24;

        #pragma unroll
        for (int j = 0; j < 4; j++) {
            const float gx = gxv[j], gy = gyv[j];
            const bool m1 = (gx * gx + gy * gy < MAXF2) && (vvv[j] != 0.0f);
            mcnt += m1 ? 1.0f : 0.0f;

            /* per-pixel shared terms */
            const float D    = a0v[j] - a1v[j];
            const float Dp   = D * L2E;
            const float lb0  = fminf(fmaxf(b2v[j], 0.0f), 10.0f);
            const float lb0p = lb0 * L2E;
            const float eb0  = exp2f(-lb0p);
            const float w    = (1.0f - eb0) * L2E;
            const float dtp  = Dp - lb0p;
            const float base = fmaf(LN2,
                                    __log2f(1.0f + exp2f(-fabsf(Dp))) + 1.0f,
                                    fmaxf(D, 0.0f));

            /* x component */
            const float dx  = fabsf(gx - fxv[j]);
            const float Sx  = fmaf(dx, w, dtp);
            const float rx  = fmaxf(Sx, 0.0f) + __log2f(1.0f + exp2f(-fabsf(Sx)));
            const float nfx = fmaf(-LN2, rx, base + dx);

            /* y component */
            const float dy  = fabsf(gy - fyv[j]);
            const float Sy  = fmaf(dy, w, dtp);
            const float ry  = fmaxf(Sy, 0.0f) + __log2f(1.0f + exp2f(-fabsf(Sy)));
            const float nfy = fmaf(-LN2, ry, base + dy);

            const bool okx = isfinite(nfx) && m1;
            const bool oky = isfinite(nfy) && m1;
            sum += okx ? nfx : 0.0f;
            sum += oky ? nfy : 0.0f;
            cnt += okx ? 1.0f : 0.0f;
            cnt += oky ? 1.0f : 0.0f;
        }
    }

    /* ---- block reduction ---- */
    #pragma unroll
    for (int o = 16; o > 0; o >>= 1) {
        sum  += __shfl_down_sync(0xFFFFFFFFu, sum,  o);
        cnt  += __shfl_down_sync(0xFFFFFFFFu, cnt,  o);
        mcnt += __shfl_down_sync(0xFFFFFFFFu, mcnt, o);
    }
    __shared__ float ssum[NTHR / 32], scnt[NTHR / 32], smc[NTHR / 32];
    const int wid  = threadIdx.x >> 5;
    const int lane = threadIdx.x & 31;
    if (lane == 0) { ssum[wid] = sum; scnt[wid] = cnt; smc[wid] = mcnt; }
    __syncthreads();

    const int pblk = b * NBXH + blockIdx.x;   /* 0..191 partial slot */
    if (threadIdx.x == 0) {
        float bs = 0.0f, bc = 0.0f, bm = 0.0f;
        #pragma unroll
        for (int w2 = 0; w2 < NTHR / 32; w2++) { bs += ssum[w2]; bc += scnt[w2]; bm += smc[w2]; }
        g_psum[n * NBX + pblk] = bs;
        g_pcnt[n * NBX + pblk] = bc;
        if (n == 0) g_pmask[pblk] = bm;
    }

    /* ---- last-block-done final reduction (deterministic: fixed partials,
            fixed reduction order; only the reducing block's identity varies) ---- */
    __shared__ unsigned s_islast;
    __threadfence();
    if (threadIdx.x == 0) {
        unsigned tkt = atomicAdd(&g_ticket, 1u);
        s_islast = (tkt == (unsigned)(NPRED_ * NBX - 1)) ? 1u : 0u;
    }
    __syncthreads();
    if (!s_islast) return;

    const int t = threadIdx.x;
    __shared__ float s_res[NPRED_];
    __shared__ float s_m[2];

    if (t < 192) {
        /* 16 threads per pred, each sums 12 partials */
        const int pred = t >> 4;
        const int sub  = t & 15;
        float s = 0.0f, c = 0.0f;
        #pragma unroll
        for (int i = sub; i < NBX; i += 16) {
            s += g_psum[pred * NBX + i];
            c += g_pcnt[pred * NBX + i];
        }
        #pragma unroll
        for (int o = 8; o > 0; o >>= 1) {
            s += __shfl_down_sync(0xFFFFFFFFu, s, o, 16);
            c += __shfl_down_sync(0xFFFFFFFFu, c, o, 16);
        }
        if (sub == 0) s_res[pred] = s / fmaxf(c, 1.0f);
    } else {
        /* threads 192..255 reduce the 192 mask partials */
        const int i0 = t - 192;
        float m = 0.0f;
        #pragma unroll
        for (int i = i0; i < NBX; i += 64) m += g_pmask[i];
        #pragma unroll
        for (int o = 16; o > 0; o >>= 1) m += __shfl_down_sync(0xFFFFFFFFu, m, o);
        if (((t - 192) & 31) == 0) s_m[(t - 192) >> 5] = m;
    }
    __syncthreads();
    if (t == 0) {
        float loss = 0.0f;
        #pragma unroll
        for (int i = 0; i < NPRED_; i++) loss += s_res[i];
        const float mean_mask = (s_m[0] + s_m[1]) * (1.0f / (float)(B_ * HW_));
        out[0] = (mean_mask < 0.25f) ? 0.0f : loss;
        g_ticket = 0;   /* reset for the next graph replay */
    }
}

extern "C" void kernel_launch(void* const* d_in, const int* in_sizes, int n_in,
                              void* d_out, int out_size) {
    const float* flow  = (const float*)d_in[0];  /* flow_preds (12,4,2,384,512) */
    const float* info  = (const float*)d_in[1];  /* info_preds (12,4,4,384,512) */
    const float* gt    = (const float*)d_in[2];  /* flow_gt    (4,2,384,512)    */
    const float* valid = (const float*)d_in[3];  /* valid      (4,1,384,512)    */
    (void)in_sizes; (void)n_in; (void)out_size;

    dim3 grid(NBXH, NPRED_, B_);
    loss_fused_kernel<<<grid, NTHR>>>(flow, info, gt, valid, (float*)d_out);
}

// round 6
// speedup vs baseline: 1.0598x; 1.0251x over previous
#include <cuda_runtime.h>
#include <math.h>

#define H_      384
#define W_      512
#define HW_     (H_ * W_)        /* 196608 */
#define HW4_    (HW_ / 4)        /* 49152 float4 groups per (n,b) plane */
#define B_      4
#define NPRED_  12
#define NBXH    96               /* blocks along hw per batch */
#define NBLK    (NBXH * B_)      /* 384 blocks total */
#define NTHR    256

/* per-block partials — device globals, no allocation */
__device__ float    g_psum[NBLK];
__device__ float    g_pmask[NBLK];
__device__ unsigned g_ticket;    /* zero-initialized; reset by last block */

/* Exact simplifications used:
   1) log_b[:,1] = clip(info[:,3], 0, 0) == 0 for finite inputs -> channel 3
      never read; lb1 = 0, exp(-lb1) = 1.
   2) For finite O(1) inputs every nf is finite (no overflow path), so
      cnt_n = 2*mask_total for every pred n, hence
      loss = sum_n sum_n/cnt_n = total_sum / max(2*mask_total, 1).
   Log2-domain algebra (D = a0-a1, lb0 = clip(info2,0,10)):
     nf_c = base + d_c - ln2*( relu(S_c) + log2(1 + 2^-|S_c|) )
     S_c  = dtp + d_c*w,  dtp = (D-lb0)*log2e,  w = (1-2^(-lb0*log2e))*log2e
     base = relu(D) + ln2*( log2(1 + 2^-|D*log2e|) + 1 )                      */

__global__ __launch_bounds__(NTHR, 4) void loss_fused_kernel(
    const float* __restrict__ flow,   /* (12,4,2,H,W) */
    const float* __restrict__ info,   /* (12,4,4,H,W) */
    const float* __restrict__ gt,     /* (4,2,H,W) */
    const float* __restrict__ valid,  /* (4,1,H,W) */
    float* __restrict__ out)
{
    const int b = blockIdx.z;
    const float L2E   = 1.44269504088896340736f;  /* log2(e) */
    const float LN2   = 0.69314718055994530942f;
    const float MAXF2 = (float)(H_ * W_);

    const float* __restrict__ gtx   = gt    + (size_t)(b * 2 + 0) * HW_;
    const float* __restrict__ gty   = gt    + (size_t)(b * 2 + 1) * HW_;
    const float* __restrict__ vld   = valid + (size_t)b * HW_;
    const float* __restrict__ fbase = flow  + (size_t)(b * 2) * HW_;  /* +n*8*HW */
    const float* __restrict__ ibase = info  + (size_t)(b * 4) * HW_;  /* +n*16*HW */

    float sum  = 0.0f;
    float mcnt = 0.0f;

    #pragma unroll
    for (int gi = 0; gi < 2; gi++) {
        const int hw = (blockIdx.x * NTHR + threadIdx.x + gi * NBXH * NTHR) * 4;

        /* gt/valid: loaded ONCE per pixel (shared by all 12 preds) */
        const float4 gx4 = __ldg((const float4*)(gtx + hw));
        const float4 gy4 = __ldg((const float4*)(gty + hw));
        const float4 vv4 = __ldg((const float4*)(vld + hw));

        float gxv[4], gyv[4], vvv[4];
        *(float4*)gxv = gx4;  *(float4*)gyv = gy4;  *(float4*)vvv = vv4;

        bool m1[4];
        #pragma unroll
        for (int j = 0; j < 4; j++) {
            m1[j] = (gxv[j] * gxv[j] + gyv[j] * gyv[j] < MAXF2) && (vvv[j] != 0.0f);
            mcnt += m1[j] ? 1.0f : 0.0f;
        }

        const float* fp = fbase + hw;
        const float* ip = ibase + hw;

        #pragma unroll 2
        for (int n = 0; n < NPRED_; n++) {
            const float4 fx4 = __ldcs((const float4*)fp);
            const float4 fy4 = __ldcs((const float4*)(fp + HW_));
            const float4 a04 = __ldcs((const float4*)ip);
            const float4 a14 = __ldcs((const float4*)(ip + HW_));
            const float4 b24 = __ldcs((const float4*)(ip + 2 * (size_t)HW_));
            fp += (size_t)B_ * 2 * HW_;
            ip += (size_t)B_ * 4 * HW_;

            float fxv[4], fyv[4], a0v[4], a1v[4], b2v[4];
            *(float4*)fxv = fx4;  *(float4*)fyv = fy4;
            *(float4*)a0v = a04;  *(float4*)a1v = a14;  *(float4*)b2v = b24;

            #pragma unroll
            for (int j = 0; j < 4; j++) {
                const float D    = a0v[j] - a1v[j];
                const float Dp   = D * L2E;
                const float lb0  = fminf(fmaxf(b2v[j], 0.0f), 10.0f);
                const float lb0p = lb0 * L2E;
                const float eb0  = exp2f(-lb0p);
                const float w    = (1.0f - eb0) * L2E;
                const float dtp  = Dp - lb0p;
                const float base = fmaf(LN2,
                                        __log2f(1.0f + exp2f(-fabsf(Dp))) + 1.0f,
                                        fmaxf(D, 0.0f));

                const float dx  = fabsf(gxv[j] - fxv[j]);
                const float Sx  = fmaf(dx, w, dtp);
                const float rx  = fmaxf(Sx, 0.0f) + __log2f(1.0f + exp2f(-fabsf(Sx)));
                const float nfx = fmaf(-LN2, rx, base + dx);

                const float dy  = fabsf(gyv[j] - fyv[j]);
                const float Sy  = fmaf(dy, w, dtp);
                const float ry  = fmaxf(Sy, 0.0f) + __log2f(1.0f + exp2f(-fabsf(Sy)));
                const float nfy = fmaf(-LN2, ry, base + dy);

                sum += m1[j] ? (nfx + nfy) : 0.0f;
            }
        }
    }

    /* ---- block reduction (sum, mcnt) ---- */
    #pragma unroll
    for (int o = 16; o > 0; o >>= 1) {
        sum  += __shfl_down_sync(0xFFFFFFFFu, sum,  o);
        mcnt += __shfl_down_sync(0xFFFFFFFFu, mcnt, o);
    }
    __shared__ float ssum[NTHR / 32], smc[NTHR / 32];
    const int wid  = threadIdx.x >> 5;
    const int lane = threadIdx.x & 31;
    if (lane == 0) { ssum[wid] = sum; smc[wid] = mcnt; }
    __syncthreads();

    const int pblk = b * NBXH + blockIdx.x;   /* 0..383 */
    if (threadIdx.x == 0) {
        float bs = 0.0f, bm = 0.0f;
        #pragma unroll
        for (int w2 = 0; w2 < NTHR / 32; w2++) { bs += ssum[w2]; bm += smc[w2]; }
        g_psum[pblk]  = bs;
        g_pmask[pblk] = bm;
    }

    /* ---- last-block-done final reduction (deterministic: fixed partials,
            fixed order; only the reducing block's identity varies) ---- */
    __shared__ unsigned s_islast;
    __threadfence();
    if (threadIdx.x == 0) {
        unsigned tkt = atomicAdd(&g_ticket, 1u);
        s_islast = (tkt == (unsigned)(NBLK - 1)) ? 1u : 0u;
    }
    __syncthreads();
    if (!s_islast) return;

    const int t = threadIdx.x;
    float fs = g_psum[t]  + ((t < NBLK - NTHR) ? g_psum[t + NTHR]  : 0.0f);
    float fm = g_pmask[t] + ((t < NBLK - NTHR) ? g_pmask[t + NTHR] : 0.0f);
    #pragma unroll
    for (int o = 16; o > 0; o >>= 1) {
        fs += __shfl_down_sync(0xFFFFFFFFu, fs, o);
        fm += __shfl_down_sync(0xFFFFFFFFu, fm, o);
    }
    __shared__ float fsum[NTHR / 32], fmk[NTHR / 32];
    if (lane == 0) { fsum[wid] = fs; fmk[wid] = fm; }
    __syncthreads();
    if (t == 0) {
        float S = 0.0f, M = 0.0f;
        #pragma unroll
        for (int w2 = 0; w2 < NTHR / 32; w2++) { S += fsum[w2]; M += fmk[w2]; }
        const float loss      = S / fmaxf(2.0f * M, 1.0f);
        const float mean_mask = M * (1.0f / (float)(B_ * HW_));
        out[0] = (mean_mask < 0.25f) ? 0.0f : loss;
        g_ticket = 0;   /* reset for the next graph replay */
    }
}

extern "C" void kernel_launch(void* const* d_in, const int* in_sizes, int n_in,
                              void* d_out, int out_size) {
    const float* flow  = (const float*)d_in[0];  /* flow_preds (12,4,2,384,512) */
    const float* info  = (const float*)d_in[1];  /* info_preds (12,4,4,384,512) */
    const float* gt    = (const float*)d_in[2];  /* flow_gt    (4,2,384,512)    */
    const float* valid = (const float*)d_in[3];  /* valid      (4,1,384,512)    */
    (void)in_sizes; (void)n_in; (void)out_size;

    dim3 grid(NBXH, 1, B_);
    loss_fused_kernel<<<grid, NTHR>>>(flow, info, gt, valid, (float*)d_out);
}